// round 13
// baseline (speedup 1.0000x reference)
#include <cuda_runtime.h>
#include <math_constants.h>

// Problem constants
#define NROWS 1048576
#define HDIM  128
#define NSEG  128
#define NEG_SLOPE 0.01f
#define LOG2E 1.4426950408889634f

// Tiling — R12/R3 structure, chunk halved for load balance
#define ROWS_PER_WARP 128
#define ROWS_PER_ITER 8
#define NUM_ITERS (ROWS_PER_WARP / ROWS_PER_ITER)     // 16
#define WARPS_PER_BLOCK 4
#define THREADS_PER_BLOCK (WARPS_PER_BLOCK * 32)      // 128
#define NUM_WARPS (NROWS / ROWS_PER_WARP)             // 8192
#define NUM_BLOCKS (NUM_WARPS / WARPS_PER_BLOCK)      // 2048

// Scratch (device globals)
__device__ float g_qs[NSEG];                 // q_score * LOG2E
__device__ float g_d[NSEG];                  // sum of exp
__device__ float g_acc[NSEG * HDIM];         // sum of exp * h

// ---------------------------------------------------------------------------
// Kernel 1: q_score[b] = (attention_query[b] . w[H:2H]) * LOG2E; zero accums.
// ---------------------------------------------------------------------------
__global__ void __launch_bounds__(HDIM)
prep_kernel(const float* __restrict__ aq, const float* __restrict__ w)
{
    const int b = blockIdx.x;
    const int t = threadIdx.x;
    const int lane = t & 31;
    g_acc[b * HDIM + t] = 0.f;
    if (t == 0) g_d[b] = 0.f;

    float v = aq[(size_t)b * HDIM + t] * w[HDIM + t];
#pragma unroll
    for (int off = 16; off; off >>= 1)
        v += __shfl_xor_sync(0xffffffffu, v, off);
    __shared__ float sm[4];
    if (lane == 0) sm[t >> 5] = v;
    __syncthreads();
    if (t == 0) g_qs[b] = ((sm[0] + sm[1]) + (sm[2] + sm[3])) * LOG2E;
}

// ---------------------------------------------------------------------------
// Process one batch of 8 rows (fast path). Lane l owns columns [4l, 4l+4).
// ---------------------------------------------------------------------------
__device__ __forceinline__ void process8(const float4 hv[ROWS_PER_ITER],
                                         float4& acc, float& d,
                                         float qsc, float4 w4, int lane)
{
    float p[8];
#pragma unroll
    for (int j = 0; j < 8; j++)
        p[j] = fmaf(hv[j].x, w4.x,
               fmaf(hv[j].y, w4.y,
               fmaf(hv[j].z, w4.z, hv[j].w * w4.w)));

    // Lane-group tree reduce (17 SHFL total instead of 40)
    const bool h16 = (lane & 16) != 0;
    const bool h8  = (lane & 8)  != 0;
    const bool h4b = (lane & 4)  != 0;

    float a[4];
#pragma unroll
    for (int j = 0; j < 4; j++) {
        float send = h16 ? p[j]     : p[j + 4];
        float keep = h16 ? p[j + 4] : p[j];
        a[j] = keep + __shfl_xor_sync(0xffffffffu, send, 16);
    }
    float bb[2];
#pragma unroll
    for (int j = 0; j < 2; j++) {
        float send = h8 ? a[j]     : a[j + 2];
        float keep = h8 ? a[j + 2] : a[j];
        bb[j] = keep + __shfl_xor_sync(0xffffffffu, send, 8);
    }
    {
        float send = h4b ? bb[0] : bb[1];
        float keep = h4b ? bb[1] : bb[0];
        float c = keep + __shfl_xor_sync(0xffffffffu, send, 4);
        c += __shfl_xor_sync(0xffffffffu, c, 2);
        c += __shfl_xor_sync(0xffffffffu, c, 1);
        p[0] = c;   // lane 4j holds full sum for row j
    }

    float e[8];
#pragma unroll
    for (int j = 0; j < 8; j++) {
        float g = __shfl_sync(0xffffffffu, p[0], j * 4) + qsc;
        g = fmaxf(g, NEG_SLOPE * g);
        e[j] = exp2f(g);
    }

    d += ((e[0] + e[1]) + (e[2] + e[3])) + ((e[4] + e[5]) + (e[6] + e[7]));

#define WSUM_COMP(comp)                                            \
    do {                                                           \
        float s0 = fmaf(e[1], hv[1].comp, e[0] * hv[0].comp);      \
        float s1 = fmaf(e[3], hv[3].comp, e[2] * hv[2].comp);      \
        float s2 = fmaf(e[5], hv[5].comp, e[4] * hv[4].comp);      \
        float s3 = fmaf(e[7], hv[7].comp, e[6] * hv[6].comp);      \
        acc.comp += (s0 + s1) + (s2 + s3);                         \
    } while (0)
    WSUM_COMP(x); WSUM_COMP(y); WSUM_COMP(z); WSUM_COMP(w);
#undef WSUM_COMP
}

// Atomic flush of a partial (d, acc) into segment accumulators.
__device__ __forceinline__ void flush_atomic(int segid, float d, float4 acc,
                                             int lane)
{
    if (lane == 0) atomicAdd(&g_d[segid], d);
    float* dst = g_acc + (size_t)segid * HDIM + lane * 4;
    atomicAdd(dst + 0, acc.x);
    atomicAdd(dst + 1, acc.y);
    atomicAdd(dst + 2, acc.z);
    atomicAdd(dst + 3, acc.w);
}

// ---------------------------------------------------------------------------
// Kernel 2: single-pass segment softmax-sum. One warp streams 128 contiguous
// rows with double-buffered 8-row batches (R3-proven loop, half chunk).
// ---------------------------------------------------------------------------
__global__ void __launch_bounds__(THREADS_PER_BLOCK)
gate_pool_kernel(const float4* __restrict__ h4,
                 const float*  __restrict__ w,
                 const int*    __restrict__ seg)
{
    const int lane = threadIdx.x & 31;
    const int warp_gid = blockIdx.x * WARPS_PER_BLOCK + (threadIdx.x >> 5);
    const int row0 = warp_gid * ROWS_PER_WARP;
    const size_t stride = HDIM / 4;   // float4 per row

    float4 w4 = reinterpret_cast<const float4*>(w)[lane];
    w4.x *= LOG2E; w4.y *= LOG2E; w4.z *= LOG2E; w4.w *= LOG2E;

    float4 acc = make_float4(0.f, 0.f, 0.f, 0.f);
    float d = 0.f;
    int cur = seg[row0];
    const int last = seg[row0 + ROWS_PER_WARP - 1];
    const float4* base = h4 + (size_t)row0 * stride + lane;

    if (cur == last) {
        // ---------------- FAST PATH: single segment in chunk ----------------
        const float qsc = g_qs[cur];
        float4 A[ROWS_PER_ITER], B[ROWS_PER_ITER];

#pragma unroll
        for (int j = 0; j < ROWS_PER_ITER; j++)
            A[j] = __ldcs(base + (size_t)j * stride);

        for (int it = 0; it < NUM_ITERS; it += 2) {
            const float4* pB = base + (size_t)(it + 1) * ROWS_PER_ITER * stride;
#pragma unroll
            for (int j = 0; j < ROWS_PER_ITER; j++)
                B[j] = __ldcs(pB + (size_t)j * stride);

            process8(A, acc, d, qsc, w4, lane);

            if (it + 2 < NUM_ITERS) {
                const float4* pA = base + (size_t)(it + 2) * ROWS_PER_ITER * stride;
#pragma unroll
                for (int j = 0; j < ROWS_PER_ITER; j++)
                    A[j] = __ldcs(pA + (size_t)j * stride);
            }

            process8(B, acc, d, qsc, w4, lane);
        }
        flush_atomic(cur, d, acc, lane);
    } else {
        // ---------------- SLOW PATH: boundary inside chunk ------------------
        float qsc = g_qs[cur];
        for (int r = row0; r < row0 + ROWS_PER_WARP; r += ROWS_PER_ITER) {
            float4 hv[ROWS_PER_ITER];
#pragma unroll
            for (int j = 0; j < ROWS_PER_ITER; j++)
                hv[j] = __ldcs(base + (size_t)(r - row0 + j) * stride);

            int s8 = seg[r + (lane & 7)];

            float g[ROWS_PER_ITER];
#pragma unroll
            for (int j = 0; j < ROWS_PER_ITER; j++) {
                float p = fmaf(hv[j].x, w4.x,
                          fmaf(hv[j].y, w4.y,
                          fmaf(hv[j].z, w4.z, hv[j].w * w4.w)));
#pragma unroll
                for (int off = 16; off; off >>= 1)
                    p += __shfl_xor_sync(0xffffffffu, p, off);
                g[j] = p;
            }

#pragma unroll
            for (int j = 0; j < ROWS_PER_ITER; j++) {
                int s = __shfl_sync(0xffffffffu, s8, j);
                if (s != cur) {
                    flush_atomic(cur, d, acc, lane);
                    d = 0.f;
                    acc = make_float4(0.f, 0.f, 0.f, 0.f);
                    cur = s;
                    qsc = g_qs[s];
                }
                float gate = g[j] + qsc;
                gate = fmaxf(gate, NEG_SLOPE * gate);
                float e = exp2f(gate);
                d += e;
                acc.x = fmaf(e, hv[j].x, acc.x);
                acc.y = fmaf(e, hv[j].y, acc.y);
                acc.z = fmaf(e, hv[j].z, acc.z);
                acc.w = fmaf(e, hv[j].w, acc.w);
            }
        }
        flush_atomic(cur, d, acc, lane);
    }
}

// ---------------------------------------------------------------------------
// Kernel 3: out[b][t] = acc[b][t] / max(d[b], 1e-20).
// ---------------------------------------------------------------------------
__global__ void __launch_bounds__(HDIM)
finalize_kernel(float* __restrict__ out)
{
    const int b = blockIdx.x;
    const int t = threadIdx.x;
    out[(size_t)b * HDIM + t] =
        g_acc[(size_t)b * HDIM + t] / fmaxf(g_d[b], 1e-20f);
}

// ---------------------------------------------------------------------------
// Launch: inputs per metadata order: h, attention_query, w, segment_ids.
// ---------------------------------------------------------------------------
extern "C" void kernel_launch(void* const* d_in, const int* in_sizes, int n_in,
                              void* d_out, int out_size)
{
    const float* h   = (const float*)d_in[0];
    const float* aq  = (const float*)d_in[1];
    const float* w   = (const float*)d_in[2];
    const int*   seg = (const int*)d_in[3];
    float* out = (float*)d_out;

    prep_kernel<<<NSEG, HDIM>>>(aq, w);
    gate_pool_kernel<<<NUM_BLOCKS, THREADS_PER_BLOCK>>>(
        (const float4*)h, w, seg);
    finalize_kernel<<<NSEG, HDIM>>>(out);
}

// round 14
// speedup vs baseline: 1.0592x; 1.0592x over previous
#include <cuda_runtime.h>
#include <math_constants.h>

// Problem constants
#define NROWS 1048576
#define HDIM  128
#define NSEG  128
#define NEG_SLOPE 0.01f
#define LOG2E 1.4426950408889634f

// Tiling — R3/R12-proven configuration
#define ROWS_PER_WARP 256
#define ROWS_PER_ITER 8
#define NUM_ITERS (ROWS_PER_WARP / ROWS_PER_ITER)     // 32
#define WARPS_PER_BLOCK 4
#define THREADS_PER_BLOCK (WARPS_PER_BLOCK * 32)      // 128
#define NUM_WARPS (NROWS / ROWS_PER_WARP)             // 4096
#define NUM_BLOCKS (NUM_WARPS / WARPS_PER_BLOCK)      // 1024

// Scratch (device globals — zero at start: .bss initially, finalize re-zeros)
__device__ float g_d[NSEG];                  // sum of exp
__device__ float g_acc[NSEG * HDIM];         // sum of exp * h

// ---------------------------------------------------------------------------
// Warp-collective q_score for segment s: (aq[s] . w_q) * LOG2E.
// ---------------------------------------------------------------------------
__device__ __forceinline__ float warp_qscore(const float4* __restrict__ aq4,
                                             const float*  __restrict__ w,
                                             int s, int lane)
{
    float4 a  = aq4[(size_t)s * (HDIM / 4) + lane];
    float4 wq = reinterpret_cast<const float4*>(w + HDIM)[lane];
    float p = fmaf(a.x, wq.x, fmaf(a.y, wq.y, fmaf(a.z, wq.z, a.w * wq.w)));
#pragma unroll
    for (int off = 16; off; off >>= 1)
        p += __shfl_xor_sync(0xffffffffu, p, off);
    return p * LOG2E;
}

// ---------------------------------------------------------------------------
// Process one batch of 8 rows (R3-proven). Lane l owns columns [4l, 4l+4).
// ---------------------------------------------------------------------------
__device__ __forceinline__ void process8(const float4 hv[ROWS_PER_ITER],
                                         float4& acc, float& d,
                                         float qsc, float4 w4, int lane)
{
    float p[8];
#pragma unroll
    for (int j = 0; j < 8; j++)
        p[j] = fmaf(hv[j].x, w4.x,
               fmaf(hv[j].y, w4.y,
               fmaf(hv[j].z, w4.z, hv[j].w * w4.w)));

    // Lane-group tree reduce (17 SHFL total)
    const bool h16 = (lane & 16) != 0;
    const bool h8  = (lane & 8)  != 0;
    const bool h4b = (lane & 4)  != 0;

    float a[4];
#pragma unroll
    for (int j = 0; j < 4; j++) {
        float send = h16 ? p[j]     : p[j + 4];
        float keep = h16 ? p[j + 4] : p[j];
        a[j] = keep + __shfl_xor_sync(0xffffffffu, send, 16);
    }
    float bb[2];
#pragma unroll
    for (int j = 0; j < 2; j++) {
        float send = h8 ? a[j]     : a[j + 2];
        float keep = h8 ? a[j + 2] : a[j];
        bb[j] = keep + __shfl_xor_sync(0xffffffffu, send, 8);
    }
    {
        float send = h4b ? bb[0] : bb[1];
        float keep = h4b ? bb[1] : bb[0];
        float c = keep + __shfl_xor_sync(0xffffffffu, send, 4);
        c += __shfl_xor_sync(0xffffffffu, c, 2);
        c += __shfl_xor_sync(0xffffffffu, c, 1);
        p[0] = c;   // lane 4j holds full sum for row j
    }

    float e[8];
#pragma unroll
    for (int j = 0; j < 8; j++) {
        float g = __shfl_sync(0xffffffffu, p[0], j * 4) + qsc;
        g = fmaxf(g, NEG_SLOPE * g);
        e[j] = exp2f(g);
    }

    d += ((e[0] + e[1]) + (e[2] + e[3])) + ((e[4] + e[5]) + (e[6] + e[7]));

#define WSUM_COMP(comp)                                            \
    do {                                                           \
        float s0 = fmaf(e[1], hv[1].comp, e[0] * hv[0].comp);      \
        float s1 = fmaf(e[3], hv[3].comp, e[2] * hv[2].comp);      \
        float s2 = fmaf(e[5], hv[5].comp, e[4] * hv[4].comp);      \
        float s3 = fmaf(e[7], hv[7].comp, e[6] * hv[6].comp);      \
        acc.comp += (s0 + s1) + (s2 + s3);                         \
    } while (0)
    WSUM_COMP(x); WSUM_COMP(y); WSUM_COMP(z); WSUM_COMP(w);
#undef WSUM_COMP
}

// Atomic flush of a partial (d, acc) into segment accumulators.
__device__ __forceinline__ void flush_atomic(int segid, float d, float4 acc,
                                             int lane)
{
    if (lane == 0) atomicAdd(&g_d[segid], d);
    float* dst = g_acc + (size_t)segid * HDIM + lane * 4;
    atomicAdd(dst + 0, acc.x);
    atomicAdd(dst + 1, acc.y);
    atomicAdd(dst + 2, acc.z);
    atomicAdd(dst + 3, acc.w);
}

// ---------------------------------------------------------------------------
// Kernel 1: single-pass segment softmax-sum. One warp streams 256 contiguous
// rows with double-buffered 8-row batches; q_score computed inline per warp,
// issued after the first load batch so its latency hides under streaming.
// ---------------------------------------------------------------------------
__global__ void __launch_bounds__(THREADS_PER_BLOCK)
gate_pool_kernel(const float4* __restrict__ h4,
                 const float4* __restrict__ aq4,
                 const float*  __restrict__ w,
                 const int*    __restrict__ seg)
{
    const int lane = threadIdx.x & 31;
    const int warp_gid = blockIdx.x * WARPS_PER_BLOCK + (threadIdx.x >> 5);
    const int row0 = warp_gid * ROWS_PER_WARP;
    const size_t stride = HDIM / 4;   // float4 per row

    float4 w4 = reinterpret_cast<const float4*>(w)[lane];
    w4.x *= LOG2E; w4.y *= LOG2E; w4.z *= LOG2E; w4.w *= LOG2E;

    float4 acc = make_float4(0.f, 0.f, 0.f, 0.f);
    float d = 0.f;
    int cur = seg[row0];
    const int last = seg[row0 + ROWS_PER_WARP - 1];
    const float4* base = h4 + (size_t)row0 * stride + lane;

    if (cur == last) {
        // ---------------- FAST PATH: single segment in chunk ----------------
        float4 A[ROWS_PER_ITER], B[ROWS_PER_ITER];

        // Issue first h batch, THEN compute qscore (latency overlapped).
#pragma unroll
        for (int j = 0; j < ROWS_PER_ITER; j++)
            A[j] = __ldcs(base + (size_t)j * stride);

        const float qsc = warp_qscore(aq4, w, cur, lane);

        for (int it = 0; it < NUM_ITERS; it += 2) {
            const float4* pB = base + (size_t)(it + 1) * ROWS_PER_ITER * stride;
#pragma unroll
            for (int j = 0; j < ROWS_PER_ITER; j++)
                B[j] = __ldcs(pB + (size_t)j * stride);

            process8(A, acc, d, qsc, w4, lane);

            if (it + 2 < NUM_ITERS) {
                const float4* pA = base + (size_t)(it + 2) * ROWS_PER_ITER * stride;
#pragma unroll
                for (int j = 0; j < ROWS_PER_ITER; j++)
                    A[j] = __ldcs(pA + (size_t)j * stride);
            }

            process8(B, acc, d, qsc, w4, lane);
        }
        flush_atomic(cur, d, acc, lane);
    } else {
        // ---------------- SLOW PATH: boundary inside chunk ------------------
        float qsc = warp_qscore(aq4, w, cur, lane);
        for (int r = row0; r < row0 + ROWS_PER_WARP; r += ROWS_PER_ITER) {
            float4 hv[ROWS_PER_ITER];
#pragma unroll
            for (int j = 0; j < ROWS_PER_ITER; j++)
                hv[j] = __ldcs(base + (size_t)(r - row0 + j) * stride);

            int s8 = seg[r + (lane & 7)];

            float g[ROWS_PER_ITER];
#pragma unroll
            for (int j = 0; j < ROWS_PER_ITER; j++) {
                float p = fmaf(hv[j].x, w4.x,
                          fmaf(hv[j].y, w4.y,
                          fmaf(hv[j].z, w4.z, hv[j].w * w4.w)));
#pragma unroll
                for (int off = 16; off; off >>= 1)
                    p += __shfl_xor_sync(0xffffffffu, p, off);
                g[j] = p;
            }

#pragma unroll
            for (int j = 0; j < ROWS_PER_ITER; j++) {
                int s = __shfl_sync(0xffffffffu, s8, j);
                if (s != cur) {
                    flush_atomic(cur, d, acc, lane);
                    d = 0.f;
                    acc = make_float4(0.f, 0.f, 0.f, 0.f);
                    cur = s;
                    qsc = warp_qscore(aq4, w, s, lane);
                }
                float gate = g[j] + qsc;
                gate = fmaxf(gate, NEG_SLOPE * gate);
                float e = exp2f(gate);
                d += e;
                acc.x = fmaf(e, hv[j].x, acc.x);
                acc.y = fmaf(e, hv[j].y, acc.y);
                acc.z = fmaf(e, hv[j].z, acc.z);
                acc.w = fmaf(e, hv[j].w, acc.w);
            }
        }
        flush_atomic(cur, d, acc, lane);
    }
}

// ---------------------------------------------------------------------------
// Kernel 2: out[b][t] = acc[b][t] / max(d[b], 1e-20); then re-zero scratch
// so the next launch/replay starts clean (deterministic).
// ---------------------------------------------------------------------------
__global__ void __launch_bounds__(HDIM)
finalize_kernel(float* __restrict__ out)
{
    const int b = blockIdx.x;
    const int t = threadIdx.x;
    const size_t idx = (size_t)b * HDIM + t;
    out[idx] = g_acc[idx] / fmaxf(g_d[b], 1e-20f);
    g_acc[idx] = 0.f;
    if (t == 0) g_d[b] = 0.f;
}

// ---------------------------------------------------------------------------
// Launch: inputs per metadata order: h, attention_query, w, segment_ids.
// ---------------------------------------------------------------------------
extern "C" void kernel_launch(void* const* d_in, const int* in_sizes, int n_in,
                              void* d_out, int out_size)
{
    const float* h   = (const float*)d_in[0];
    const float* aq  = (const float*)d_in[1];
    const float* w   = (const float*)d_in[2];
    const int*   seg = (const int*)d_in[3];
    float* out = (float*)d_out;

    gate_pool_kernel<<<NUM_BLOCKS, THREADS_PER_BLOCK>>>(
        (const float4*)h, (const float4*)aq, w, seg);
    finalize_kernel<<<NSEG, HDIM>>>(out);
}